// round 4
// baseline (speedup 1.0000x reference)
#include <cuda_runtime.h>
#include <cstdint>

#define B 16
#define G 128
#define P 8000
#define R 200
#define POS_CAP 66
#define NSORT 8192
#define K1_SPLITS 8
#define K1_CHUNK 1000
#define NBINS 2048
#define CAND_CAP 1024

// ---------------- scratch (no allocations allowed) ----------------
__device__ unsigned long long d_gbest[B * G];
__device__ int d_gt_argmax[B * G];
__device__ float d_pmax[B * P];
__device__ int d_parg[B * P];
__device__ unsigned long long d_poskeys[B * NSORT];
__device__ unsigned long long d_negkeys[B * NSORT];
__device__ int d_poscount[B];
__device__ int d_negcount[B];
__device__ int d_posidx[B * POS_CAP];
__device__ int d_negidx[B * R];

// ---------------- threefry2x32 (exact JAX) ----------------
__device__ __forceinline__ uint32_t rotl32(uint32_t v, int d) {
    return (v << d) | (v >> (32 - d));
}

__device__ __forceinline__ void threefry(uint32_t k0, uint32_t k1, uint32_t x0,
                                         uint32_t x1, uint32_t& o0, uint32_t& o1) {
    uint32_t ks2 = k0 ^ k1 ^ 0x1BD11BDAu;
    x0 += k0; x1 += k1;
#define TFR(r) { x0 += x1; x1 = rotl32(x1, r); x1 ^= x0; }
    TFR(13) TFR(15) TFR(26) TFR(6)
    x0 += k1; x1 += ks2 + 1u;
    TFR(17) TFR(29) TFR(16) TFR(24)
    x0 += ks2; x1 += k0 + 2u;
    TFR(13) TFR(15) TFR(26) TFR(6)
    x0 += k0; x1 += k1 + 3u;
    TFR(17) TFR(29) TFR(16) TFR(24)
    x0 += k1; x1 += ks2 + 4u;
    TFR(13) TFR(15) TFR(26) TFR(6)
    x0 += ks2; x1 += k0 + 5u;
#undef TFR
    o0 = x0; o1 = x1;
}

// ---- JAX threefry_partitionable (default since 0.4.36) key derivation ----
// split(key, n) fold-like: key_m = threefry(key, hi64(m)=0, lo=m) -> (o0, o1)
// per-batch keys k1 (pos sampling), k2 (neg sampling)
__device__ __forceinline__ void batch_keys(int b, uint32_t& k1a, uint32_t& k1b,
                                           uint32_t& k2a, uint32_t& k2b) {
    uint32_t kb0, kb1;
    threefry(0u, 42u, 0u, (uint32_t)b, kb0, kb1);   // split(key(42), 16)[b]
    threefry(kb0, kb1, 0u, 0u, k1a, k1b);           // split(key_b, 2)[0]
    threefry(kb0, kb1, 0u, 1u, k2a, k2b);           // split(key_b, 2)[1]
}

// uniform(key, (8000,))[p]: partitionable random_bits = o0 ^ o1 of
// threefry(key, counter_hi=0, counter_lo=p)
__device__ __forceinline__ float u01(uint32_t ka, uint32_t kb, int p) {
    uint32_t a, c;
    threefry(ka, kb, 0u, (uint32_t)p, a, c);
    uint32_t bits = a ^ c;
    return __uint_as_float(0x3f800000u | (bits >> 9)) - 1.0f;
}

// order-preserving float->uint map
__device__ __forceinline__ uint32_t ford(float f) {
    uint32_t u = __float_as_uint(f);
    return (u & 0x80000000u) ? ~u : (u | 0x80000000u);
}

// ---------------- K0: reset per-gt best keys ----------------
__global__ void k0_init() {
    int i = blockIdx.x * blockDim.x + threadIdx.x;
    if (i < B * G) d_gbest[i] = 0ull;
}

// ---------------- K1: IoU + dual reductions ----------------
__global__ void k1_iou(const float* __restrict__ gt, const float* __restrict__ pr) {
    int b = blockIdx.y;
    int split = blockIdx.x;
    int tid = threadIdx.x;

    __shared__ float sg0[G], sg1[G], sg2[G], sg3[G], sga[G];
    __shared__ unsigned char sgv[G];
    __shared__ unsigned long long sbest[G];

    if (tid < G) {
        const float* gp = gt + ((size_t)b * G + tid) * 5;
        float a0 = gp[0], a1 = gp[1], a2 = gp[2], a3 = gp[3], a4 = gp[4];
        sg0[tid] = a0; sg1[tid] = a1; sg2[tid] = a2; sg3[tid] = a3;
        sga[tid] = __fmul_rn(__fsub_rn(a3, a1), __fsub_rn(a2, a0));
        sgv[tid] = (a4 != 0.0f) ? 1 : 0;
        sbest[tid] = 0ull;
    }
    __syncthreads();

    int p = split * K1_CHUNK + tid;
    bool act = (tid < K1_CHUNK) && (p < P);
    float p0 = 0, p1 = 0, p2 = 0, p3 = 0, ap = 0;
    bool pv = false;
    if (act) {
        const float* pp = pr + ((size_t)b * P + p) * 5;
        p0 = pp[0]; p1 = pp[1]; p2 = pp[2]; p3 = pp[3];
        pv = (pp[4] != 0.0f);
        ap = __fmul_rn(__fsub_rn(p3, p1), __fsub_rn(p2, p0));
    }

    float best = -2.0f;
    int barg = 0;
    uint32_t plow = 0xFFFFFFFFu - (uint32_t)p;

    for (int g = 0; g < G; ++g) {
        float iw = fmaxf(0.0f, __fsub_rn(fminf(sg3[g], p3), fmaxf(sg1[g], p1)));
        float ih = fmaxf(0.0f, __fsub_rn(fminf(sg2[g], p2), fmaxf(sg0[g], p0)));
        float inter = __fmul_rn(iw, ih);
        float denom = __fsub_rn(__fadd_rn(sga[g], ap), inter);
        float iou = __fdiv_rn(inter, denom);
        bool valid = act && pv && (sgv[g] != 0);
        float v = valid ? iou : -1.0f;
        if (v > best) { best = v; barg = g; }  // first-index argmax over g

        unsigned long long key =
            act ? ((((unsigned long long)ford(v)) << 32) | (unsigned long long)plow) : 0ull;
        // warp-level max reduce of packed key
        #pragma unroll
        for (int off = 16; off > 0; off >>= 1) {
            unsigned long long o = __shfl_down_sync(0xFFFFFFFFu, key, off);
            if (o > key) key = o;
        }
        if ((tid & 31) == 0 && key != 0ull) atomicMax(&sbest[g], key);
    }

    if (act) {
        d_pmax[(size_t)b * P + p] = best;
        d_parg[(size_t)b * P + p] = barg;
    }
    __syncthreads();
    if (tid < G && sbest[tid] != 0ull)
        atomicMax(&d_gbest[(size_t)b * G + tid], sbest[tid]);
}

// ---------------- K2: extract gt_argmax (valid gts only) ----------------
__global__ void k2_argmax(const float* __restrict__ gt) {
    int b = blockIdx.x;
    int g = threadIdx.x;
    if (g < G) {
        unsigned long long key = d_gbest[b * G + g];
        int arg = (int)(0xFFFFFFFFu - (uint32_t)(key & 0xFFFFFFFFull));
        float tag = gt[((size_t)b * G + g) * 5 + 4];
        d_gt_argmax[b * G + g] = (tag != 0.0f) ? arg : -1;
    }
}

// ---------------- K3: masks, RNG keys, counts, miss ----------------
__global__ void k3_flags(const float* __restrict__ gt, const float* __restrict__ pr,
                         float* __restrict__ miss_out) {
    int b = blockIdx.x;
    int tid = threadIdx.x;  // 1024 threads

    __shared__ int s_arg[G];
    __shared__ unsigned char s_gv[G];
    __shared__ unsigned char s_matched[G];
    __shared__ uint32_t s_rem[P / 32];  // 250 words removed-bitmap
    __shared__ int s_npos, s_nneg, s_miss;

    for (int i = tid; i < P / 32; i += blockDim.x) s_rem[i] = 0u;
    if (tid < G) {
        s_arg[tid] = d_gt_argmax[b * G + tid];
        s_gv[tid] = (gt[((size_t)b * G + tid) * 5 + 4] != 0.0f) ? 1 : 0;
        s_matched[tid] = 0;
    }
    if (tid == 0) { s_npos = 0; s_nneg = 0; s_miss = 0; }
    __syncthreads();

    if (tid < G) {
        int a = s_arg[tid];
        if (a >= 0) atomicOr(&s_rem[a >> 5], 1u << (a & 31));
    }
    __syncthreads();

    uint32_t k1a, k1b, k2a, k2b;
    batch_keys(b, k1a, k1b, k2a, k2b);

    int npos_local = 0, nneg_local = 0;
    for (int p = tid; p < NSORT; p += blockDim.x) {
        unsigned long long pk = 0ull, nk = 0ull;
        if (p < P) {
            bool removed = ((s_rem[p >> 5] >> (p & 31)) & 1u) != 0;
            bool pv = (pr[((size_t)b * P + p) * 5 + 4] != 0.0f);
            float pm = d_pmax[(size_t)b * P + p];
            bool keep = pv && !removed;
            bool pos = keep && (pm >= 0.5f);
            bool neg = keep && (pm < 0.5f);
            uint32_t plow = 0xFFFFFFFFu - (uint32_t)p;
            if (pos) {
                float u = u01(k1a, k1b, p);
                pk = (((unsigned long long)ford(u)) << 32) | (unsigned long long)plow;
                npos_local++;
                s_matched[d_parg[(size_t)b * P + p]] = 1;
            }
            if (neg) {
                float u = u01(k2a, k2b, p);
                nk = (((unsigned long long)ford(u)) << 32) | (unsigned long long)plow;
                nneg_local++;
            }
        }
        d_poskeys[(size_t)b * NSORT + p] = pk;
        d_negkeys[(size_t)b * NSORT + p] = nk;
    }
    if (npos_local) atomicAdd(&s_npos, npos_local);
    if (nneg_local) atomicAdd(&s_nneg, nneg_local);
    __syncthreads();

    if (tid < G) {
        if (s_gv[tid] && !s_matched[tid]) atomicAdd(&s_miss, 1);
    }
    __syncthreads();
    if (tid == 0) {
        d_poscount[b] = s_npos;
        d_negcount[b] = s_nneg;
        miss_out[b] = (float)s_miss;
    }
}

// ---------------- K4: exact top-K select (histogram + candidate sort) ----
// Static smem only (~33KB), no cudaFuncSetAttribute needed.
__global__ void k4_select() {
    __shared__ uint32_t hist[NBINS];
    __shared__ uint32_t sfx[NBINS];
    __shared__ uint32_t sfx2[NBINS];
    __shared__ unsigned long long cand[CAND_CAP];
    __shared__ int s_T, s_cnt;

    int b = blockIdx.y;
    bool isPos = (blockIdx.x == 0);
    int K = isPos ? POS_CAP : R;
    const unsigned long long* src =
        isPos ? (d_poskeys + (size_t)b * NSORT) : (d_negkeys + (size_t)b * NSORT);
    int tid = threadIdx.x;  // 1024

    for (int i = tid; i < NBINS; i += blockDim.x) hist[i] = 0u;
    if (tid == 0) { s_T = 0; s_cnt = 0; }
    __syncthreads();

    // histogram of high-32 bits (only nonzero keys are eligible)
    for (int p = tid; p < NSORT; p += blockDim.x) {
        unsigned long long key = src[p];
        if (key != 0ull) {
            uint32_t hi = (uint32_t)(key >> 32);
            uint32_t bin = (hi - 0x80000000u) >> 19;  // [0, 2032]
            atomicAdd(&hist[bin], 1u);
        }
    }
    __syncthreads();

    // inclusive suffix sum (Hillis-Steele, ping-pong)
    for (int i = tid; i < NBINS; i += blockDim.x) sfx[i] = hist[i];
    __syncthreads();
    uint32_t* cur = sfx;
    uint32_t* nxt = sfx2;
    for (int d = 1; d < NBINS; d <<= 1) {
        for (int i = tid; i < NBINS; i += blockDim.x) {
            uint32_t v = cur[i];
            if (i + d < NBINS) v += cur[i + d];
            nxt[i] = v;
        }
        __syncthreads();
        uint32_t* t = cur; cur = nxt; nxt = t;
    }

    // threshold bin: largest T with suffix(T) >= K; if total < K, T stays 0
    for (int i = tid; i < NBINS; i += blockDim.x) {
        if (cur[i] >= (uint32_t)K && (i == NBINS - 1 || cur[i + 1] < (uint32_t)K))
            s_T = i;
    }
    __syncthreads();
    int T = s_T;

    // gather candidates (all keys with bin >= T); exact top-K is a subset
    for (int p = tid; p < NSORT; p += blockDim.x) {
        unsigned long long key = src[p];
        if (key != 0ull) {
            uint32_t hi = (uint32_t)(key >> 32);
            int bin = (int)((hi - 0x80000000u) >> 19);
            if (bin >= T) {
                int pos = atomicAdd(&s_cnt, 1);
                if (pos < CAND_CAP) cand[pos] = key;
            }
        }
    }
    __syncthreads();
    int cnt = min(s_cnt, CAND_CAP);
    for (int i = cnt + tid; i < CAND_CAP; i += blockDim.x) cand[i] = 0ull;
    __syncthreads();

    // bitonic sort CAND_CAP u64 keys, descending
    for (int k = 2; k <= CAND_CAP; k <<= 1) {
        for (int j = k >> 1; j > 0; j >>= 1) {
            int i = tid;
            if (i < CAND_CAP) {
                int ixj = i ^ j;
                if (ixj > i) {
                    unsigned long long a = cand[i], c = cand[ixj];
                    bool up = ((i & k) == 0);
                    if (up ? (a < c) : (a > c)) { cand[i] = c; cand[ixj] = a; }
                }
            }
            __syncthreads();
        }
    }

    if (tid < K) {
        unsigned long long key = cand[tid];
        uint32_t pp = 0xFFFFFFFFu - (uint32_t)(key & 0xFFFFFFFFull);
        if (key == 0ull || pp >= (uint32_t)P) pp = 0;  // dead slots, never dereferenced
        if (isPos) d_posidx[b * POS_CAP + tid] = (int)pp;
        else       d_negidx[b * R + tid] = (int)pp;
    }
}

// ---------------- K5: gather + regression targets + emit ----------------
__global__ void k5_out(const float* __restrict__ gt, const int* __restrict__ gcls,
                       const float* __restrict__ pr, float* __restrict__ out) {
    int b = blockIdx.x;
    int s = threadIdx.x;
    if (s >= R) return;

    int np = min(d_poscount[b], POS_CAP);
    int nn = min(R - np, d_negcount[b]);

    float de0 = 0, de1 = 0, de2 = 0, de3 = 0, de4 = 0;
    float c0 = 0, c1 = 0;
    float r0 = 0, r1 = 0, r2 = 0, r3 = 0, r4 = 0;

    bool is_pos = s < np;
    bool is_real = s < np + nn;

    if (is_real) {
        int idx = is_pos ? d_posidx[b * POS_CAP + s] : d_negidx[b * R + (s - np)];
        const float* pp = pr + ((size_t)b * P + idx) * 5;
        r0 = pp[0]; r1 = pp[1]; r2 = pp[2]; r3 = pp[3]; r4 = 1.0f;
        c1 = 1.0f;
        if (is_pos) {
            int g = d_parg[(size_t)b * P + idx];
            const float* gp = gt + ((size_t)b * G + g) * 5;
            float g0 = gp[0], g1 = gp[1], g2 = gp[2], g3 = gp[3];
            float h = r2 - r0, w = r3 - r1;
            float gh = g2 - g0, gw = g3 - g1;
            float cy = (r2 + r0) * 0.5f, cx = (r3 + r1) * 0.5f;
            float gcy = (g2 + g0) * 0.5f, gcx = (g3 + g1) * 0.5f;
            de0 = ((gcy - cy) / h) / 0.1f;
            de1 = ((gcx - cx) / w) / 0.1f;
            de2 = logf(fmaxf(gh / h, 1e-8f)) / 0.2f;
            de3 = logf(fmaxf(gw / w, 1e-8f)) / 0.2f;
            de4 = 1.0f;
            c0 = (float)gcls[((size_t)b * G + g) * 2 + 0];
        } else {
            de4 = -1.0f;
        }
    }

    size_t sl = (size_t)b * R + s;
    float* dd = out + sl * 5;
    dd[0] = de0; dd[1] = de1; dd[2] = de2; dd[3] = de3; dd[4] = de4;
    float* cc = out + (size_t)B * R * 5 + sl * 2;
    cc[0] = c0; cc[1] = c1;
    float* rr = out + (size_t)B * R * 5 + (size_t)B * R * 2 + sl * 5;
    rr[0] = r0; rr[1] = r1; rr[2] = r2; rr[3] = r3; rr[4] = r4;
}

// ---------------- launch ----------------
extern "C" void kernel_launch(void* const* d_in, const int* in_sizes, int n_in,
                              void* d_out, int out_size) {
    const float* gt = (const float*)d_in[0];
    const int* gcls = (const int*)d_in[1];
    const float* pr = (const float*)d_in[2];
    float* out = (float*)d_out;

    float* miss_out = out + (size_t)B * R * 5 + (size_t)B * R * 2 + (size_t)B * R * 5;

    k0_init<<<(B * G + 255) / 256, 256>>>();
    k1_iou<<<dim3(K1_SPLITS, B), 1024>>>(gt, pr);
    k2_argmax<<<B, G>>>(gt);
    k3_flags<<<B, 1024>>>(gt, pr, miss_out);
    k4_select<<<dim3(2, B), 1024>>>();
    k5_out<<<B, 256>>>(gt, gcls, pr, out);
}

// round 5
// speedup vs baseline: 1.2516x; 1.2516x over previous
#include <cuda_runtime.h>
#include <cstdint>

#define B 16
#define G 128
#define P 8000
#define R 200
#define POS_CAP 66
#define NSORT 8192
#define K1_SPLITS 8
#define K1_CHUNK 1000
#define NBINS 2048
#define CAND_CAP 1024

// ---------------- scratch (no allocations allowed) ----------------
__device__ unsigned long long d_gbest[B * G];
__device__ float d_pmax[B * P];
__device__ int d_parg[B * P];
__device__ unsigned long long d_poskeys[B * NSORT];
__device__ unsigned long long d_negkeys[B * NSORT];
__device__ int d_poscount[B];
__device__ int d_negcount[B];
__device__ int d_posidx[B * POS_CAP];
__device__ int d_negidx[B * R];
__device__ int d_matched[B * G];

// ---------------- threefry2x32 (exact JAX, partitionable path) ----------
__device__ __forceinline__ uint32_t rotl32(uint32_t v, int d) {
    return (v << d) | (v >> (32 - d));
}

__device__ __forceinline__ void threefry(uint32_t k0, uint32_t k1, uint32_t x0,
                                         uint32_t x1, uint32_t& o0, uint32_t& o1) {
    uint32_t ks2 = k0 ^ k1 ^ 0x1BD11BDAu;
    x0 += k0; x1 += k1;
#define TFR(r) { x0 += x1; x1 = rotl32(x1, r); x1 ^= x0; }
    TFR(13) TFR(15) TFR(26) TFR(6)
    x0 += k1; x1 += ks2 + 1u;
    TFR(17) TFR(29) TFR(16) TFR(24)
    x0 += ks2; x1 += k0 + 2u;
    TFR(13) TFR(15) TFR(26) TFR(6)
    x0 += k0; x1 += k1 + 3u;
    TFR(17) TFR(29) TFR(16) TFR(24)
    x0 += k1; x1 += ks2 + 4u;
    TFR(13) TFR(15) TFR(26) TFR(6)
    x0 += ks2; x1 += k0 + 5u;
#undef TFR
    o0 = x0; o1 = x1;
}

// split(key, n) fold-like: key_m = threefry(key, hi64(m)=0, lo=m)
__device__ __forceinline__ void batch_keys(int b, uint32_t& k1a, uint32_t& k1b,
                                           uint32_t& k2a, uint32_t& k2b) {
    uint32_t kb0, kb1;
    threefry(0u, 42u, 0u, (uint32_t)b, kb0, kb1);   // split(key(42), 16)[b]
    threefry(kb0, kb1, 0u, 0u, k1a, k1b);           // split(key_b, 2)[0]
    threefry(kb0, kb1, 0u, 1u, k2a, k2b);           // split(key_b, 2)[1]
}

// uniform(key, (8000,))[p]: partitionable random_bits = o0 ^ o1
__device__ __forceinline__ float u01(uint32_t ka, uint32_t kb, int p) {
    uint32_t a, c;
    threefry(ka, kb, 0u, (uint32_t)p, a, c);
    uint32_t bits = a ^ c;
    return __uint_as_float(0x3f800000u | (bits >> 9)) - 1.0f;
}

// order-preserving float->uint map
__device__ __forceinline__ uint32_t ford(float f) {
    uint32_t u = __float_as_uint(f);
    return (u & 0x80000000u) ? ~u : (u | 0x80000000u);
}

// ---------------- K0: reset scratch ----------------
__global__ void k0_init() {
    int i = blockIdx.x * blockDim.x + threadIdx.x;
    if (i < B * G) { d_gbest[i] = 0ull; d_matched[i] = 0; }
    if (i < B) { d_poscount[i] = 0; d_negcount[i] = 0; }
    if (i < B * (NSORT - P)) {
        int bb = i / (NSORT - P), t = i % (NSORT - P);
        d_poskeys[(size_t)bb * NSORT + P + t] = 0ull;
        d_negkeys[(size_t)bb * NSORT + P + t] = 0ull;
    }
}

// ---------------- K1: IoU + dual reductions ----------------
__global__ void k1_iou(const float* __restrict__ gt, const float* __restrict__ pr) {
    int b = blockIdx.y;
    int split = blockIdx.x;
    int tid = threadIdx.x;
    int lane = tid & 31;

    __shared__ float sg0[G], sg1[G], sg2[G], sg3[G], sga[G];
    __shared__ unsigned char sgv[G];
    __shared__ unsigned long long sbest[G];

    if (tid < G) {
        const float* gp = gt + ((size_t)b * G + tid) * 5;
        float a0 = gp[0], a1 = gp[1], a2 = gp[2], a3 = gp[3], a4 = gp[4];
        sg0[tid] = a0; sg1[tid] = a1; sg2[tid] = a2; sg3[tid] = a3;
        sga[tid] = __fmul_rn(__fsub_rn(a3, a1), __fsub_rn(a2, a0));
        sgv[tid] = (a4 != 0.0f) ? 1 : 0;
        sbest[tid] = 0ull;
    }
    __syncthreads();

    int p = split * K1_CHUNK + tid;
    bool act = (tid < K1_CHUNK) && (p < P);
    float p0 = 0, p1 = 0, p2 = 0, p3 = 0, ap = 0;
    bool pv = false;
    if (act) {
        const float* pp = pr + ((size_t)b * P + p) * 5;
        p0 = pp[0]; p1 = pp[1]; p2 = pp[2]; p3 = pp[3];
        pv = (pp[4] != 0.0f);
        ap = __fmul_rn(__fsub_rn(p3, p1), __fsub_rn(p2, p0));
    }

    float best = -2.0f;
    int barg = 0;
    uint32_t wbase = (uint32_t)(split * K1_CHUNK + (tid & ~31));

    for (int g = 0; g < G; ++g) {
        float iw = fmaxf(0.0f, __fsub_rn(fminf(sg3[g], p3), fmaxf(sg1[g], p1)));
        float ih = fmaxf(0.0f, __fsub_rn(fminf(sg2[g], p2), fmaxf(sg0[g], p0)));
        float inter = __fmul_rn(iw, ih);
        float denom = __fsub_rn(__fadd_rn(sga[g], ap), inter);
        float iou = __fdiv_rn(inter, denom);
        bool valid = act && pv && (sgv[g] != 0);
        float v = valid ? iou : -1.0f;
        if (v > best) { best = v; barg = g; }  // first-index argmax over g

        // warp max of ford(v) (inactive lanes contribute 0)
        uint32_t fv = act ? ford(v) : 0u;
        uint32_t wmax = __reduce_max_sync(0xFFFFFFFFu, fv);
        uint32_t ball = __ballot_sync(0xFFFFFFFFu, fv == wmax && wmax != 0u);
        if (lane == 0 && ball != 0u) {
            int src = __ffs(ball) - 1;                 // lowest lane = lowest p
            uint32_t plow = 0xFFFFFFFFu - (wbase + (uint32_t)src);
            unsigned long long key =
                (((unsigned long long)wmax) << 32) | (unsigned long long)plow;
            atomicMax(&sbest[g], key);
        }
    }

    if (act) {
        d_pmax[(size_t)b * P + p] = best;
        d_parg[(size_t)b * P + p] = barg;
    }
    __syncthreads();
    if (tid < G && sbest[tid] != 0ull)
        atomicMax(&d_gbest[(size_t)b * G + tid], sbest[tid]);
}

// ---------------- K3: masks, RNG keys, counts (grid = splits x B) -------
__global__ void k3_flags(const float* __restrict__ gt, const float* __restrict__ pr) {
    int b = blockIdx.y;
    int split = blockIdx.x;
    int tid = threadIdx.x;  // 256
    int pbase = split * K1_CHUNK;

    __shared__ uint32_t s_rem[(K1_CHUNK + 31) / 32 + 1];

    if (tid < (K1_CHUNK + 31) / 32 + 1) s_rem[tid] = 0u;
    __syncthreads();

    // removed bits within this block's p-range, from gbest directly
    if (tid < G) {
        if (gt[((size_t)b * G + tid) * 5 + 4] != 0.0f) {
            unsigned long long key = d_gbest[b * G + tid];
            int arg = (int)(0xFFFFFFFFu - (uint32_t)(key & 0xFFFFFFFFull));
            int rel = arg - pbase;
            if (rel >= 0 && rel < K1_CHUNK)
                atomicOr(&s_rem[rel >> 5], 1u << (rel & 31));
        }
    }
    __syncthreads();

    uint32_t k1a, k1b, k2a, k2b;
    batch_keys(b, k1a, k1b, k2a, k2b);

    int nposl = 0, nnegl = 0;
    for (int i = tid; i < K1_CHUNK; i += blockDim.x) {
        int p = pbase + i;
        unsigned long long pk = 0ull, nk = 0ull;
        bool removed = ((s_rem[i >> 5] >> (i & 31)) & 1u) != 0;
        bool pv = (pr[((size_t)b * P + p) * 5 + 4] != 0.0f);
        float pm = d_pmax[(size_t)b * P + p];
        bool keep = pv && !removed;
        uint32_t plow = 0xFFFFFFFFu - (uint32_t)p;
        if (keep) {
            if (pm >= 0.5f) {
                float u = u01(k1a, k1b, p);
                pk = (((unsigned long long)ford(u)) << 32) | (unsigned long long)plow;
                nposl++;
                d_matched[b * G + d_parg[(size_t)b * P + p]] = 1;
            } else {
                float u = u01(k2a, k2b, p);
                nk = (((unsigned long long)ford(u)) << 32) | (unsigned long long)plow;
                nnegl++;
            }
        }
        d_poskeys[(size_t)b * NSORT + p] = pk;
        d_negkeys[(size_t)b * NSORT + p] = nk;
    }

    // warp-aggregate then one atomic per warp
    nposl = __reduce_add_sync(0xFFFFFFFFu, nposl);
    nnegl = __reduce_add_sync(0xFFFFFFFFu, nnegl);
    if ((tid & 31) == 0) {
        if (nposl) atomicAdd(&d_poscount[b], nposl);
        if (nnegl) atomicAdd(&d_negcount[b], nnegl);
    }
}

// ---------------- K4: exact top-K select (histogram + rank-by-count) ----
__global__ void k4_select() {
    __shared__ uint32_t hist[NBINS];
    __shared__ uint32_t sfx[NBINS];
    __shared__ uint32_t sfx2[NBINS];
    __shared__ unsigned long long cand[CAND_CAP];
    __shared__ uint32_t cand_p[CAND_CAP];
    __shared__ int s_T, s_cnt;

    int b = blockIdx.y;
    bool isPos = (blockIdx.x == 0);
    int K = isPos ? POS_CAP : R;
    const unsigned long long* src =
        isPos ? (d_poskeys + (size_t)b * NSORT) : (d_negkeys + (size_t)b * NSORT);
    int tid = threadIdx.x;  // 1024

    for (int i = tid; i < NBINS; i += blockDim.x) hist[i] = 0u;
    if (tid == 0) { s_T = 0; s_cnt = 0; }
    __syncthreads();

    // histogram of high-32 bits (only nonzero keys are eligible)
    for (int p = tid; p < NSORT; p += blockDim.x) {
        unsigned long long key = src[p];
        if (key != 0ull) {
            uint32_t hi = (uint32_t)(key >> 32);
            uint32_t bin = (hi - 0x80000000u) >> 19;
            atomicAdd(&hist[bin], 1u);
        }
    }
    __syncthreads();

    // inclusive suffix sum (Hillis-Steele, ping-pong)
    for (int i = tid; i < NBINS; i += blockDim.x) sfx[i] = hist[i];
    __syncthreads();
    uint32_t* cur = sfx;
    uint32_t* nxt = sfx2;
    for (int d = 1; d < NBINS; d <<= 1) {
        for (int i = tid; i < NBINS; i += blockDim.x) {
            uint32_t v = cur[i];
            if (i + d < NBINS) v += cur[i + d];
            nxt[i] = v;
        }
        __syncthreads();
        uint32_t* t = cur; cur = nxt; nxt = t;
    }

    // threshold bin: largest T with suffix(T) >= K; if total < K, T stays 0
    for (int i = tid; i < NBINS; i += blockDim.x) {
        if (cur[i] >= (uint32_t)K && (i == NBINS - 1 || cur[i + 1] < (uint32_t)K))
            s_T = i;
    }
    __syncthreads();
    int T = s_T;

    // gather candidates (all keys with bin >= T); exact top-K is a subset
    for (int p = tid; p < NSORT; p += blockDim.x) {
        unsigned long long key = src[p];
        if (key != 0ull) {
            uint32_t hi = (uint32_t)(key >> 32);
            int bin = (int)((hi - 0x80000000u) >> 19);
            if (bin >= T) {
                int pos = atomicAdd(&s_cnt, 1);
                if (pos < CAND_CAP) {
                    cand[pos] = key;
                    cand_p[pos] = (uint32_t)p;
                }
            }
        }
    }
    __syncthreads();
    int cnt = min(s_cnt, CAND_CAP);

    // rank-by-count: keys are distinct (distinct low-word), so ranks are a
    // permutation; rank r < K writes output slot r. Slots >= n_real are
    // never read by K5.
    for (int i = tid; i < cnt; i += blockDim.x) {
        unsigned long long ki = cand[i];
        int rank = 0;
        for (int j = 0; j < cnt; ++j) rank += (cand[j] > ki) ? 1 : 0;
        if (rank < K) {
            if (isPos) d_posidx[b * POS_CAP + rank] = (int)cand_p[i];
            else       d_negidx[b * R + rank] = (int)cand_p[i];
        }
    }
}

// ---------------- K5: gather + regression targets + emit + miss --------
__global__ void k5_out(const float* __restrict__ gt, const int* __restrict__ gcls,
                       const float* __restrict__ pr, float* __restrict__ out,
                       float* __restrict__ miss_out) {
    int b = blockIdx.x;
    int tid = threadIdx.x;  // 256

    __shared__ int s_miss;
    if (tid == 0) s_miss = 0;
    __syncthreads();

    if (tid < G) {
        if (gt[((size_t)b * G + tid) * 5 + 4] != 0.0f && d_matched[b * G + tid] == 0)
            atomicAdd(&s_miss, 1);
    }

    int s = tid;
    if (s < R) {
        int np = min(d_poscount[b], POS_CAP);
        int nn = min(R - np, d_negcount[b]);

        float de0 = 0, de1 = 0, de2 = 0, de3 = 0, de4 = 0;
        float c0 = 0, c1 = 0;
        float r0 = 0, r1 = 0, r2 = 0, r3 = 0, r4 = 0;

        bool is_pos = s < np;
        bool is_real = s < np + nn;

        if (is_real) {
            int idx = is_pos ? d_posidx[b * POS_CAP + s] : d_negidx[b * R + (s - np)];
            const float* pp = pr + ((size_t)b * P + idx) * 5;
            r0 = pp[0]; r1 = pp[1]; r2 = pp[2]; r3 = pp[3]; r4 = 1.0f;
            c1 = 1.0f;
            if (is_pos) {
                int g = d_parg[(size_t)b * P + idx];
                const float* gp = gt + ((size_t)b * G + g) * 5;
                float g0 = gp[0], g1 = gp[1], g2 = gp[2], g3 = gp[3];
                float h = r2 - r0, w = r3 - r1;
                float gh = g2 - g0, gw = g3 - g1;
                float cy = (r2 + r0) * 0.5f, cx = (r3 + r1) * 0.5f;
                float gcy = (g2 + g0) * 0.5f, gcx = (g3 + g1) * 0.5f;
                de0 = ((gcy - cy) / h) / 0.1f;
                de1 = ((gcx - cx) / w) / 0.1f;
                de2 = logf(fmaxf(gh / h, 1e-8f)) / 0.2f;
                de3 = logf(fmaxf(gw / w, 1e-8f)) / 0.2f;
                de4 = 1.0f;
                c0 = (float)gcls[((size_t)b * G + g) * 2 + 0];
            } else {
                de4 = -1.0f;
            }
        }

        size_t sl = (size_t)b * R + s;
        float* dd = out + sl * 5;
        dd[0] = de0; dd[1] = de1; dd[2] = de2; dd[3] = de3; dd[4] = de4;
        float* cc = out + (size_t)B * R * 5 + sl * 2;
        cc[0] = c0; cc[1] = c1;
        float* rr = out + (size_t)B * R * 5 + (size_t)B * R * 2 + sl * 5;
        rr[0] = r0; rr[1] = r1; rr[2] = r2; rr[3] = r3; rr[4] = r4;
    }

    __syncthreads();
    if (tid == 0) miss_out[b] = (float)s_miss;
}

// ---------------- launch ----------------
extern "C" void kernel_launch(void* const* d_in, const int* in_sizes, int n_in,
                              void* d_out, int out_size) {
    const float* gt = (const float*)d_in[0];
    const int* gcls = (const int*)d_in[1];
    const float* pr = (const float*)d_in[2];
    float* out = (float*)d_out;

    float* miss_out = out + (size_t)B * R * 5 + (size_t)B * R * 2 + (size_t)B * R * 5;

    k0_init<<<12, 256>>>();
    k1_iou<<<dim3(K1_SPLITS, B), 1024>>>(gt, pr);
    k3_flags<<<dim3(K1_SPLITS, B), 256>>>(gt, pr);
    k4_select<<<dim3(2, B), 1024>>>();
    k5_out<<<B, 256>>>(gt, gcls, pr, out, miss_out);
}

// round 6
// speedup vs baseline: 1.4053x; 1.1228x over previous
#include <cuda_runtime.h>
#include <cstdint>

#define B 16
#define G 128
#define P 8000
#define R 200
#define POS_CAP 66
#define K1_SPLITS 8
#define K1_CHUNK 1000
#define NBINS 2048
#define CAND_CAP 1024
#define NB 128   // persistent blocks (co-resident: 1 block/SM x 148 SMs >= 128)

// ---------------- scratch (no allocations allowed) ----------------
__device__ unsigned long long d_gbest[B * G];
__device__ float d_pmax[B * P];
__device__ int d_parg[B * P];
__device__ unsigned long long d_poskeys[B * P];
__device__ unsigned long long d_negkeys[B * P];
__device__ int d_poscount[B];
__device__ int d_negcount[B];
__device__ int d_posidx[B * POS_CAP];
__device__ int d_negidx[B * R];
__device__ int d_matched[B * G];
__device__ volatile unsigned d_bar;

// ---------------- threefry2x32 (exact JAX, partitionable path) ----------
__device__ __forceinline__ uint32_t rotl32(uint32_t v, int d) {
    return (v << d) | (v >> (32 - d));
}

__device__ __forceinline__ void threefry(uint32_t k0, uint32_t k1, uint32_t x0,
                                         uint32_t x1, uint32_t& o0, uint32_t& o1) {
    uint32_t ks2 = k0 ^ k1 ^ 0x1BD11BDAu;
    x0 += k0; x1 += k1;
#define TFR(r) { x0 += x1; x1 = rotl32(x1, r); x1 ^= x0; }
    TFR(13) TFR(15) TFR(26) TFR(6)
    x0 += k1; x1 += ks2 + 1u;
    TFR(17) TFR(29) TFR(16) TFR(24)
    x0 += ks2; x1 += k0 + 2u;
    TFR(13) TFR(15) TFR(26) TFR(6)
    x0 += k0; x1 += k1 + 3u;
    TFR(17) TFR(29) TFR(16) TFR(24)
    x0 += k1; x1 += ks2 + 4u;
    TFR(13) TFR(15) TFR(26) TFR(6)
    x0 += ks2; x1 += k0 + 5u;
#undef TFR
    o0 = x0; o1 = x1;
}

__device__ __forceinline__ void batch_keys(int b, uint32_t& k1a, uint32_t& k1b,
                                           uint32_t& k2a, uint32_t& k2b) {
    uint32_t kb0, kb1;
    threefry(0u, 42u, 0u, (uint32_t)b, kb0, kb1);   // split(key(42), 16)[b]
    threefry(kb0, kb1, 0u, 0u, k1a, k1b);           // split(key_b, 2)[0]
    threefry(kb0, kb1, 0u, 1u, k2a, k2b);           // split(key_b, 2)[1]
}

__device__ __forceinline__ float u01(uint32_t ka, uint32_t kb, int p) {
    uint32_t a, c;
    threefry(ka, kb, 0u, (uint32_t)p, a, c);
    uint32_t bits = a ^ c;
    return __uint_as_float(0x3f800000u | (bits >> 9)) - 1.0f;
}

__device__ __forceinline__ uint32_t ford(float f) {
    uint32_t u = __float_as_uint(f);
    return (u & 0x80000000u) ? ~u : (u | 0x80000000u);
}

// ---------------- software grid barrier ----------------
__device__ __forceinline__ void gsync(unsigned target) {
    __syncthreads();
    if (threadIdx.x == 0) {
        __threadfence();
        atomicAdd((unsigned*)&d_bar, 1u);
        while (d_bar < target) __nanosleep(64);
        __threadfence();   // CCTL.IVALL on sm_103: no stale L1 after barrier
    }
    __syncthreads();
}

// ---------------- init: re-zero accumulators each launch ----------------
__global__ void k_init() {
    int i = blockIdx.x * blockDim.x + threadIdx.x;
    if (i == 0) *(unsigned*)&d_bar = 0u;
    if (i < B * G) { d_gbest[i] = 0ull; d_matched[i] = 0; }
    if (i < B) { d_poscount[i] = 0; d_negcount[i] = 0; }
}

// ---------------- persistent main kernel ----------------
__global__ __launch_bounds__(1024, 1)
void k_main(const float* __restrict__ gt, const int* __restrict__ gcls,
            const float* __restrict__ pr, float* __restrict__ out,
            float* __restrict__ miss_out) {
    __shared__ __align__(16) unsigned char s_raw[36864];
    __shared__ int s_wcnt[4], s_woff[4], s_ng;
    __shared__ uint32_t s_rem[32];
    __shared__ int s_T, s_cnt, s_miss;

    int bid = blockIdx.x;
    int tid = threadIdx.x;
    int lane = tid & 31;
    int wid = tid >> 5;

    // ================= Phase 1: IoU + dual reductions =================
    {
        int b = bid >> 3;
        int split = bid & 7;

        float* sg0 = (float*)s_raw;
        float* sg1 = sg0 + G;
        float* sg2 = sg1 + G;
        float* sg3 = sg2 + G;
        float* sga = sg3 + G;
        int* sglist = (int*)(sga + G);
        unsigned long long* sbest = (unsigned long long*)(s_raw + 3584);

        // load gts + compact valid (order-preserving)
        bool gvalid = false;
        float a0 = 0, a1 = 0, a2 = 0, a3 = 0;
        if (tid < G) {
            const float* gp = gt + ((size_t)b * G + tid) * 5;
            a0 = gp[0]; a1 = gp[1]; a2 = gp[2]; a3 = gp[3];
            gvalid = (gp[4] != 0.0f);
            sbest[tid] = 0ull;
        }
        if (tid < G) {
            unsigned ball = __ballot_sync(0xFFFFFFFFu, gvalid);
            if (lane == 0) s_wcnt[wid] = __popc(ball);
        }
        __syncthreads();
        if (tid == 0) {
            int off = 0;
            for (int w = 0; w < 4; ++w) { s_woff[w] = off; off += s_wcnt[w]; }
            s_ng = off;
        }
        __syncthreads();
        if (tid < G && gvalid) {
            unsigned ball = __ballot_sync(__activemask(), true);
            // rank within warp among valid lanes below me
            unsigned below = ball & ((1u << lane) - 1u);
            int rank = s_woff[wid] + __popc(below);
            sg0[rank] = a0; sg1[rank] = a1; sg2[rank] = a2; sg3[rank] = a3;
            sga[rank] = __fmul_rn(__fsub_rn(a3, a1), __fsub_rn(a2, a0));
            sglist[rank] = tid;
        }
        __syncthreads();
        int ng = s_ng;

        int p = split * K1_CHUNK + tid;
        bool act = (tid < K1_CHUNK);
        float p0 = 0, p1 = 0, p2 = 0, p3 = 0, ap = 0;
        bool pv = false;
        if (act) {
            const float* pp = pr + ((size_t)b * P + p) * 5;
            p0 = pp[0]; p1 = pp[1]; p2 = pp[2]; p3 = pp[3];
            pv = (pp[4] != 0.0f);
            ap = __fmul_rn(__fsub_rn(p3, p1), __fsub_rn(p2, p0));
        }

        float best = -2.0f;
        int barg = 0;
        uint32_t wbase = (uint32_t)(split * K1_CHUNK + (tid & ~31));

        for (int i = 0; i < ng; ++i) {
            float iw = fmaxf(0.0f, __fsub_rn(fminf(sg3[i], p3), fmaxf(sg1[i], p1)));
            float ih = fmaxf(0.0f, __fsub_rn(fminf(sg2[i], p2), fmaxf(sg0[i], p0)));
            float inter = __fmul_rn(iw, ih);
            float denom = __fsub_rn(__fadd_rn(sga[i], ap), inter);
            float iou = __fdiv_rn(inter, denom);
            bool valid = act && pv;
            float v = valid ? iou : -1.0f;
            if (v > best) { best = v; barg = i; }   // first-index argmax

            uint32_t fv = act ? ford(v) : 0u;
            uint32_t wmax = __reduce_max_sync(0xFFFFFFFFu, fv);
            uint32_t ball = __ballot_sync(0xFFFFFFFFu, fv == wmax && wmax != 0u);
            if (lane == 0 && ball != 0u) {
                int src = __ffs(ball) - 1;           // lowest lane = lowest p
                uint32_t plow = 0xFFFFFFFFu - (wbase + (uint32_t)src);
                unsigned long long key =
                    (((unsigned long long)wmax) << 32) | (unsigned long long)plow;
                atomicMax(&sbest[i], key);
            }
        }

        if (act) {
            d_pmax[(size_t)b * P + p] = (ng > 0) ? best : -1.0f;
            d_parg[(size_t)b * P + p] = (ng > 0) ? sglist[barg] : 0;
        }
        __syncthreads();
        if (tid < ng && sbest[tid] != 0ull)
            atomicMax(&d_gbest[(size_t)b * G + sglist[tid]], sbest[tid]);
    }

    gsync(NB);

    // ================= Phase 2: masks, RNG keys, counts =================
    {
        int b = bid >> 3;
        int split = bid & 7;
        int pbase = split * K1_CHUNK;

        if (tid < 32) s_rem[tid] = 0u;
        __syncthreads();

        if (tid < G) {
            if (gt[((size_t)b * G + tid) * 5 + 4] != 0.0f) {
                unsigned long long key = d_gbest[b * G + tid];
                int arg = (int)(0xFFFFFFFFu - (uint32_t)(key & 0xFFFFFFFFull));
                int rel = arg - pbase;
                if (rel >= 0 && rel < K1_CHUNK)
                    atomicOr(&s_rem[rel >> 5], 1u << (rel & 31));
            }
        }
        __syncthreads();

        uint32_t k1a, k1b, k2a, k2b;
        batch_keys(b, k1a, k1b, k2a, k2b);

        int nposl = 0, nnegl = 0;
        for (int i = tid; i < K1_CHUNK; i += blockDim.x) {
            int p = pbase + i;
            unsigned long long pk = 0ull, nk = 0ull;
            bool removed = ((s_rem[i >> 5] >> (i & 31)) & 1u) != 0;
            bool pv = (pr[((size_t)b * P + p) * 5 + 4] != 0.0f);
            float pm = d_pmax[(size_t)b * P + p];
            bool keep = pv && !removed;
            uint32_t plow = 0xFFFFFFFFu - (uint32_t)p;
            if (keep) {
                if (pm >= 0.5f) {
                    float u = u01(k1a, k1b, p);
                    pk = (((unsigned long long)ford(u)) << 32) | (unsigned long long)plow;
                    nposl++;
                    d_matched[b * G + d_parg[(size_t)b * P + p]] = 1;
                } else {
                    float u = u01(k2a, k2b, p);
                    nk = (((unsigned long long)ford(u)) << 32) | (unsigned long long)plow;
                    nnegl++;
                }
            }
            d_poskeys[(size_t)b * P + p] = pk;
            d_negkeys[(size_t)b * P + p] = nk;
        }

        nposl = __reduce_add_sync(0xFFFFFFFFu, nposl);
        nnegl = __reduce_add_sync(0xFFFFFFFFu, nnegl);
        if (lane == 0) {
            if (nposl) atomicAdd(&d_poscount[b], nposl);
            if (nnegl) atomicAdd(&d_negcount[b], nnegl);
        }
    }

    gsync(2 * NB);

    // ================= Phase 3: exact top-K select (32 blocks) ==========
    if (bid < 32) {
        uint32_t* hist = (uint32_t*)s_raw;
        uint32_t* sfx = hist + NBINS;
        uint32_t* sfx2 = sfx + NBINS;
        unsigned long long* cand = (unsigned long long*)(sfx2 + NBINS);
        uint32_t* cand_p = (uint32_t*)(cand + CAND_CAP);

        int b = bid >> 1;
        bool isPos = ((bid & 1) == 0);
        int K = isPos ? POS_CAP : R;
        const unsigned long long* src =
            isPos ? (d_poskeys + (size_t)b * P) : (d_negkeys + (size_t)b * P);

        for (int i = tid; i < NBINS; i += blockDim.x) hist[i] = 0u;
        if (tid == 0) { s_T = 0; s_cnt = 0; }
        __syncthreads();

        for (int p = tid; p < P; p += blockDim.x) {
            unsigned long long key = src[p];
            if (key != 0ull) {
                uint32_t hi = (uint32_t)(key >> 32);
                uint32_t bin = (hi - 0x80000000u) >> 19;
                atomicAdd(&hist[bin], 1u);
            }
        }
        __syncthreads();

        // inclusive suffix sum (Hillis-Steele ping-pong)
        for (int i = tid; i < NBINS; i += blockDim.x) sfx[i] = hist[i];
        __syncthreads();
        uint32_t* cur = sfx;
        uint32_t* nxt = sfx2;
        for (int d = 1; d < NBINS; d <<= 1) {
            for (int i = tid; i < NBINS; i += blockDim.x) {
                uint32_t v = cur[i];
                if (i + d < NBINS) v += cur[i + d];
                nxt[i] = v;
            }
            __syncthreads();
            uint32_t* t = cur; cur = nxt; nxt = t;
        }

        for (int i = tid; i < NBINS; i += blockDim.x) {
            if (cur[i] >= (uint32_t)K && (i == NBINS - 1 || cur[i + 1] < (uint32_t)K))
                s_T = i;
        }
        __syncthreads();
        int T = s_T;

        for (int p = tid; p < P; p += blockDim.x) {
            unsigned long long key = src[p];
            if (key != 0ull) {
                uint32_t hi = (uint32_t)(key >> 32);
                int bin = (int)((hi - 0x80000000u) >> 19);
                if (bin >= T) {
                    int pos = atomicAdd(&s_cnt, 1);
                    if (pos < CAND_CAP) {
                        cand[pos] = key;
                        cand_p[pos] = (uint32_t)p;
                    }
                }
            }
        }
        __syncthreads();
        int cnt = min(s_cnt, CAND_CAP);

        // rank-by-count (keys distinct): rank r < K writes output slot r
        for (int i = tid; i < cnt; i += blockDim.x) {
            unsigned long long ki = cand[i];
            int rank = 0;
            for (int j = 0; j < cnt; ++j) rank += (cand[j] > ki) ? 1 : 0;
            if (rank < K) {
                if (isPos) d_posidx[b * POS_CAP + rank] = (int)cand_p[i];
                else       d_negidx[b * R + rank] = (int)cand_p[i];
            }
        }
    }

    gsync(3 * NB);

    // ================= Phase 4: emit outputs (16 blocks) ================
    if (bid < B) {
        int b = bid;
        if (tid == 0) s_miss = 0;
        __syncthreads();

        if (tid < G) {
            if (gt[((size_t)b * G + tid) * 5 + 4] != 0.0f && d_matched[b * G + tid] == 0)
                atomicAdd(&s_miss, 1);
        }

        int s = tid;
        if (s < R) {
            int np = min(d_poscount[b], POS_CAP);
            int nn = min(R - np, d_negcount[b]);

            float de0 = 0, de1 = 0, de2 = 0, de3 = 0, de4 = 0;
            float c0 = 0, c1 = 0;
            float r0 = 0, r1 = 0, r2 = 0, r3 = 0, r4 = 0;

            bool is_pos = s < np;
            bool is_real = s < np + nn;

            if (is_real) {
                int idx = is_pos ? d_posidx[b * POS_CAP + s] : d_negidx[b * R + (s - np)];
                const float* pp = pr + ((size_t)b * P + idx) * 5;
                r0 = pp[0]; r1 = pp[1]; r2 = pp[2]; r3 = pp[3]; r4 = 1.0f;
                c1 = 1.0f;
                if (is_pos) {
                    int g = d_parg[(size_t)b * P + idx];
                    const float* gp = gt + ((size_t)b * G + g) * 5;
                    float g0 = gp[0], g1 = gp[1], g2 = gp[2], g3 = gp[3];
                    float h = r2 - r0, w = r3 - r1;
                    float gh = g2 - g0, gw = g3 - g1;
                    float cy = (r2 + r0) * 0.5f, cx = (r3 + r1) * 0.5f;
                    float gcy = (g2 + g0) * 0.5f, gcx = (g3 + g1) * 0.5f;
                    de0 = ((gcy - cy) / h) / 0.1f;
                    de1 = ((gcx - cx) / w) / 0.1f;
                    de2 = logf(fmaxf(gh / h, 1e-8f)) / 0.2f;
                    de3 = logf(fmaxf(gw / w, 1e-8f)) / 0.2f;
                    de4 = 1.0f;
                    c0 = (float)gcls[((size_t)b * G + g) * 2 + 0];
                } else {
                    de4 = -1.0f;
                }
            }

            size_t sl = (size_t)b * R + s;
            float* dd = out + sl * 5;
            dd[0] = de0; dd[1] = de1; dd[2] = de2; dd[3] = de3; dd[4] = de4;
            float* cc = out + (size_t)B * R * 5 + sl * 2;
            cc[0] = c0; cc[1] = c1;
            float* rr = out + (size_t)B * R * 5 + (size_t)B * R * 2 + sl * 5;
            rr[0] = r0; rr[1] = r1; rr[2] = r2; rr[3] = r3; rr[4] = r4;
        }

        __syncthreads();
        if (tid == 0) miss_out[b] = (float)s_miss;
    }
}

// ---------------- launch ----------------
extern "C" void kernel_launch(void* const* d_in, const int* in_sizes, int n_in,
                              void* d_out, int out_size) {
    const float* gt = (const float*)d_in[0];
    const int* gcls = (const int*)d_in[1];
    const float* pr = (const float*)d_in[2];
    float* out = (float*)d_out;

    float* miss_out = out + (size_t)B * R * 5 + (size_t)B * R * 2 + (size_t)B * R * 5;

    k_init<<<8, 256>>>();
    k_main<<<NB, 1024>>>(gt, gcls, pr, out, miss_out);
}

// round 10
// speedup vs baseline: 1.5946x; 1.1347x over previous
#include <cuda_runtime.h>
#include <cstdint>

#define B 16
#define G 128
#define P 8000
#define R 200
#define POS_CAP 66
#define NSPLIT 24
#define CHUNK 334          // 24 * 334 = 8016 >= 8000
#define NBINS 1024
#define CAND_CAP 512
#define NB 384             // persistent blocks: 148 SMs x 3 co-resident (512 thr, <=42 regs)

// ---------------- scratch (no allocations allowed) ----------------
__device__ unsigned long long d_gbest[B * G];
__device__ float d_pmax[B * P];
__device__ int d_parg[B * P];
__device__ unsigned long long d_poskeys[B * P];
__device__ unsigned long long d_negkeys[B * P];
__device__ int d_poscount[B];
__device__ int d_negcount[B];
__device__ int d_posidx[B * POS_CAP];
__device__ int d_negidx[B * R];
__device__ int d_matched[B * G];
__device__ volatile unsigned d_bar;

// ---------------- threefry2x32 (exact JAX, partitionable path) ----------
__device__ __forceinline__ uint32_t rotl32(uint32_t v, int d) {
    return (v << d) | (v >> (32 - d));
}

__device__ __forceinline__ void threefry(uint32_t k0, uint32_t k1, uint32_t x0,
                                         uint32_t x1, uint32_t& o0, uint32_t& o1) {
    uint32_t ks2 = k0 ^ k1 ^ 0x1BD11BDAu;
    x0 += k0; x1 += k1;
#define TFR(r) { x0 += x1; x1 = rotl32(x1, r); x1 ^= x0; }
    TFR(13) TFR(15) TFR(26) TFR(6)
    x0 += k1; x1 += ks2 + 1u;
    TFR(17) TFR(29) TFR(16) TFR(24)
    x0 += ks2; x1 += k0 + 2u;
    TFR(13) TFR(15) TFR(26) TFR(6)
    x0 += k0; x1 += k1 + 3u;
    TFR(17) TFR(29) TFR(16) TFR(24)
    x0 += k1; x1 += ks2 + 4u;
    TFR(13) TFR(15) TFR(26) TFR(6)
    x0 += ks2; x1 += k0 + 5u;
#undef TFR
    o0 = x0; o1 = x1;
}

__device__ __forceinline__ void batch_keys(int b, uint32_t& k1a, uint32_t& k1b,
                                           uint32_t& k2a, uint32_t& k2b) {
    uint32_t kb0, kb1;
    threefry(0u, 42u, 0u, (uint32_t)b, kb0, kb1);   // split(key(42), 16)[b]
    threefry(kb0, kb1, 0u, 0u, k1a, k1b);           // split(key_b, 2)[0]
    threefry(kb0, kb1, 0u, 1u, k2a, k2b);           // split(key_b, 2)[1]
}

// sort key: u = m * 2^-23 with m = (o0^o1)>>9 -- strictly monotonic in m,
// so sort directly on the 23-bit mantissa (uniformly distributed).
__device__ __forceinline__ uint32_t umant(uint32_t ka, uint32_t kb, int p) {
    uint32_t a, c;
    threefry(ka, kb, 0u, (uint32_t)p, a, c);
    return (a ^ c) >> 9;
}

__device__ __forceinline__ uint32_t ford(float f) {
    uint32_t u = __float_as_uint(f);
    return (u & 0x80000000u) ? ~u : (u | 0x80000000u);
}

// ---------------- software grid barrier ----------------
__device__ __forceinline__ void gsync(unsigned target) {
    __syncthreads();
    if (threadIdx.x == 0) {
        __threadfence();
        atomicAdd((unsigned*)&d_bar, 1u);
        while (d_bar < target) __nanosleep(32);
        __threadfence();
    }
    __syncthreads();
}

// ---------------- init: re-zero accumulators each launch ----------------
__global__ void k_init() {
    int i = blockIdx.x * blockDim.x + threadIdx.x;
    if (i == 0) *(unsigned*)&d_bar = 0u;
    if (i < B * G) { d_gbest[i] = 0ull; d_matched[i] = 0; }
    if (i < B) { d_poscount[i] = 0; d_negcount[i] = 0; }
}

// ---------------- persistent main kernel ----------------
__global__ __launch_bounds__(512, 3)
void k_main(const float* __restrict__ gt, const int* __restrict__ gcls,
            const float* __restrict__ pr, float* __restrict__ out,
            float* __restrict__ miss_out) {
    __shared__ __align__(16) unsigned char s_raw[18432];
    __shared__ int s_wcnt[4], s_woff[4], s_ng;
    __shared__ uint32_t s_rem[(CHUNK + 31) / 32 + 1];
    __shared__ int s_T, s_cnt, s_miss;

    int bid = blockIdx.x;
    int tid = threadIdx.x;
    int lane = tid & 31;
    int wid = tid >> 5;

    // ================= Phase 1: IoU + dual reductions =================
    {
        int b = bid / NSPLIT;
        int split = bid % NSPLIT;

        float4* sg4 = (float4*)s_raw;                       // 128*16 = 2048B
        float* sga = (float*)(s_raw + 2048);                // 512B
        int* sglist = (int*)(s_raw + 2560);                 // 512B
        unsigned long long* sbest = (unsigned long long*)(s_raw + 3072);  // 1KB

        // load gts + compact valid (order-preserving)
        bool gvalid = false;
        float a0 = 0, a1 = 0, a2 = 0, a3 = 0;
        if (tid < G) {
            const float* gp = gt + ((size_t)b * G + tid) * 5;
            a0 = gp[0]; a1 = gp[1]; a2 = gp[2]; a3 = gp[3];
            gvalid = (gp[4] != 0.0f);
            sbest[tid] = 0ull;
        }
        if (tid < G) {
            unsigned ball = __ballot_sync(0xFFFFFFFFu, gvalid);
            if (lane == 0) s_wcnt[wid] = __popc(ball);
        }
        __syncthreads();
        if (tid == 0) {
            int off = 0;
            for (int w = 0; w < 4; ++w) { s_woff[w] = off; off += s_wcnt[w]; }
            s_ng = off;
        }
        __syncthreads();
        if (tid < G && gvalid) {
            unsigned ball = __ballot_sync(__activemask(), true);
            unsigned below = ball & ((1u << lane) - 1u);
            int rank = s_woff[wid] + __popc(below);
            sg4[rank] = make_float4(a0, a1, a2, a3);
            sga[rank] = __fmul_rn(__fsub_rn(a3, a1), __fsub_rn(a2, a0));
            sglist[rank] = tid;
        }
        __syncthreads();
        int ng = s_ng;

        int p = split * CHUNK + tid;
        bool act = (tid < CHUNK) && (p < P);
        float p0 = 0, p1 = 0, p2 = 0, p3 = 0, ap = 0;
        bool pv = false;
        if (act) {
            const float* pp = pr + ((size_t)b * P + p) * 5;
            p0 = pp[0]; p1 = pp[1]; p2 = pp[2]; p3 = pp[3];
            pv = (pp[4] != 0.0f);
            ap = __fmul_rn(__fsub_rn(p3, p1), __fsub_rn(p2, p0));
        }

        float best = -2.0f;
        int barg = 0;
        uint32_t wbase = (uint32_t)(split * CHUNK + (tid & ~31));

        for (int i = 0; i < ng; ++i) {
            float4 gb = sg4[i];
            float iw = fmaxf(0.0f, __fsub_rn(fminf(gb.w, p3), fmaxf(gb.y, p1)));
            float ih = fmaxf(0.0f, __fsub_rn(fminf(gb.z, p2), fmaxf(gb.x, p0)));
            float inter = __fmul_rn(iw, ih);
            float denom = __fsub_rn(__fadd_rn(sga[i], ap), inter);
            float iou = __fdiv_rn(inter, denom);
            bool valid = act && pv;
            float v = valid ? iou : -1.0f;
            if (v > best) { best = v; barg = i; }   // first-index argmax

            uint32_t fv = valid ? ford(v) : 0u;
            uint32_t wmax = __reduce_max_sync(0xFFFFFFFFu, fv);
            uint32_t ball = __ballot_sync(0xFFFFFFFFu, fv == wmax && wmax != 0u);
            if (lane == 0 && ball != 0u) {
                int src = __ffs(ball) - 1;           // lowest lane = lowest p
                uint32_t plow = 0xFFFFFFFFu - (wbase + (uint32_t)src);
                unsigned long long key =
                    (((unsigned long long)wmax) << 32) | (unsigned long long)plow;
                atomicMax(&sbest[i], key);
            }
        }

        if (act) {
            d_pmax[(size_t)b * P + p] = (ng > 0) ? best : -1.0f;
            d_parg[(size_t)b * P + p] = (ng > 0) ? sglist[barg] : 0;
        }
        __syncthreads();
        if (tid < ng && sbest[tid] != 0ull)
            atomicMax(&d_gbest[(size_t)b * G + sglist[tid]], sbest[tid]);
    }

    gsync(NB);

    // ================= Phase 2: masks, RNG keys, counts =================
    {
        int b = bid / NSPLIT;
        int split = bid % NSPLIT;
        int pbase = split * CHUNK;
        int plim = min(CHUNK, P - pbase);

        if (tid < (CHUNK + 31) / 32 + 1) s_rem[tid] = 0u;
        __syncthreads();

        if (tid < G) {
            if (gt[((size_t)b * G + tid) * 5 + 4] != 0.0f) {
                unsigned long long key = d_gbest[b * G + tid];
                int arg = (int)(0xFFFFFFFFu - (uint32_t)(key & 0xFFFFFFFFull));
                int rel = arg - pbase;
                if (rel >= 0 && rel < CHUNK)
                    atomicOr(&s_rem[rel >> 5], 1u << (rel & 31));
            }
        }
        __syncthreads();

        uint32_t k1a, k1b, k2a, k2b;
        batch_keys(b, k1a, k1b, k2a, k2b);

        int nposl = 0, nnegl = 0;
        for (int i = tid; i < plim; i += blockDim.x) {
            int p = pbase + i;
            unsigned long long pk = 0ull, nk = 0ull;
            bool removed = ((s_rem[i >> 5] >> (i & 31)) & 1u) != 0;
            bool pv = (pr[((size_t)b * P + p) * 5 + 4] != 0.0f);
            float pm = d_pmax[(size_t)b * P + p];
            bool keep = pv && !removed;
            uint32_t plow = 0xFFFFFFFFu - (uint32_t)p;
            if (keep) {
                if (pm >= 0.5f) {
                    uint32_t m = umant(k1a, k1b, p);
                    pk = (((unsigned long long)m) << 32) | (unsigned long long)plow;
                    nposl++;
                    d_matched[b * G + d_parg[(size_t)b * P + p]] = 1;
                } else {
                    uint32_t m = umant(k2a, k2b, p);
                    nk = (((unsigned long long)m) << 32) | (unsigned long long)plow;
                    nnegl++;
                }
            }
            d_poskeys[(size_t)b * P + p] = pk;
            d_negkeys[(size_t)b * P + p] = nk;
        }

        nposl = __reduce_add_sync(0xFFFFFFFFu, nposl);
        nnegl = __reduce_add_sync(0xFFFFFFFFu, nnegl);
        if (lane == 0) {
            if (nposl) atomicAdd(&d_poscount[b], nposl);
            if (nnegl) atomicAdd(&d_negcount[b], nnegl);
        }
    }

    gsync(2 * NB);

    // ================= Phase 3: exact top-K select (32 blocks) ==========
    if (bid < 32) {
        uint32_t* hist = (uint32_t*)s_raw;                     // 4KB
        uint32_t* sfx = hist + NBINS;                          // 4KB
        uint32_t* sfx2 = sfx + NBINS;                          // 4KB
        unsigned long long* cand = (unsigned long long*)(sfx2 + NBINS);  // 4KB
        uint32_t* cand_p = (uint32_t*)(cand + CAND_CAP);       // 2KB

        int b = bid >> 1;
        bool isPos = ((bid & 1) == 0);
        int K = isPos ? POS_CAP : R;
        const unsigned long long* src =
            isPos ? (d_poskeys + (size_t)b * P) : (d_negkeys + (size_t)b * P);

        for (int i = tid; i < NBINS; i += blockDim.x) hist[i] = 0u;
        if (tid == 0) { s_T = 0; s_cnt = 0; }
        __syncthreads();

        // bin = mantissa >> 13: uniform over [0,1024) -> no atomic hotspots
        for (int p = tid; p < P; p += blockDim.x) {
            unsigned long long key = src[p];
            if (key != 0ull) {
                uint32_t bin = (uint32_t)(key >> 45);   // 23-bit m >> 13
                atomicAdd(&hist[bin], 1u);
            }
        }
        __syncthreads();

        // inclusive suffix sum (Hillis-Steele ping-pong)
        for (int i = tid; i < NBINS; i += blockDim.x) sfx[i] = hist[i];
        __syncthreads();
        uint32_t* cur = sfx;
        uint32_t* nxt = sfx2;
        for (int d = 1; d < NBINS; d <<= 1) {
            for (int i = tid; i < NBINS; i += blockDim.x) {
                uint32_t v = cur[i];
                if (i + d < NBINS) v += cur[i + d];
                nxt[i] = v;
            }
            __syncthreads();
            uint32_t* t = cur; cur = nxt; nxt = t;
        }

        for (int i = tid; i < NBINS; i += blockDim.x) {
            if (cur[i] >= (uint32_t)K && (i == NBINS - 1 || cur[i + 1] < (uint32_t)K))
                s_T = i;
        }
        __syncthreads();
        int T = s_T;

        for (int p = tid; p < P; p += blockDim.x) {
            unsigned long long key = src[p];
            if (key != 0ull) {
                int bin = (int)(key >> 45);
                if (bin >= T) {
                    int pos = atomicAdd(&s_cnt, 1);
                    if (pos < CAND_CAP) {
                        cand[pos] = key;
                        cand_p[pos] = (uint32_t)p;
                    }
                }
            }
        }
        __syncthreads();
        int cnt = min(s_cnt, CAND_CAP);

        // rank-by-count (keys distinct via low word): rank r < K -> slot r
        for (int i = tid; i < cnt; i += blockDim.x) {
            unsigned long long ki = cand[i];
            int rank = 0;
            for (int j = 0; j < cnt; ++j) rank += (cand[j] > ki) ? 1 : 0;
            if (rank < K) {
                if (isPos) d_posidx[b * POS_CAP + rank] = (int)cand_p[i];
                else       d_negidx[b * R + rank] = (int)cand_p[i];
            }
        }
    }

    gsync(3 * NB);

    // ================= Phase 4: emit outputs (16 blocks) ================
    if (bid < B) {
        int b = bid;
        if (tid == 0) s_miss = 0;
        __syncthreads();

        if (tid < G) {
            if (gt[((size_t)b * G + tid) * 5 + 4] != 0.0f && d_matched[b * G + tid] == 0)
                atomicAdd(&s_miss, 1);
        }

        int s = tid;
        if (s < R) {
            int np = min(d_poscount[b], POS_CAP);
            int nn = min(R - np, d_negcount[b]);

            float de0 = 0, de1 = 0, de2 = 0, de3 = 0, de4 = 0;
            float c0 = 0, c1 = 0;
            float r0 = 0, r1 = 0, r2 = 0, r3 = 0, r4 = 0;

            bool is_pos = s < np;
            bool is_real = s < np + nn;

            if (is_real) {
                int idx = is_pos ? d_posidx[b * POS_CAP + s] : d_negidx[b * R + (s - np)];
                const float* pp = pr + ((size_t)b * P + idx) * 5;
                r0 = pp[0]; r1 = pp[1]; r2 = pp[2]; r3 = pp[3]; r4 = 1.0f;
                c1 = 1.0f;
                if (is_pos) {
                    int g = d_parg[(size_t)b * P + idx];
                    const float* gp = gt + ((size_t)b * G + g) * 5;
                    float g0 = gp[0], g1 = gp[1], g2 = gp[2], g3 = gp[3];
                    float h = r2 - r0, w = r3 - r1;
                    float gh = g2 - g0, gw = g3 - g1;
                    float cy = (r2 + r0) * 0.5f, cx = (r3 + r1) * 0.5f;
                    float gcy = (g2 + g0) * 0.5f, gcx = (g3 + g1) * 0.5f;
                    de0 = ((gcy - cy) / h) / 0.1f;
                    de1 = ((gcx - cx) / w) / 0.1f;
                    de2 = logf(fmaxf(gh / h, 1e-8f)) / 0.2f;
                    de3 = logf(fmaxf(gw / w, 1e-8f)) / 0.2f;
                    de4 = 1.0f;
                    c0 = (float)gcls[((size_t)b * G + g) * 2 + 0];
                } else {
                    de4 = -1.0f;
                }
            }

            size_t sl = (size_t)b * R + s;
            float* dd = out + sl * 5;
            dd[0] = de0; dd[1] = de1; dd[2] = de2; dd[3] = de3; dd[4] = de4;
            float* cc = out + (size_t)B * R * 5 + sl * 2;
            cc[0] = c0; cc[1] = c1;
            float* rr = out + (size_t)B * R * 5 + (size_t)B * R * 2 + sl * 5;
            rr[0] = r0; rr[1] = r1; rr[2] = r2; rr[3] = r3; rr[4] = r4;
        }

        __syncthreads();
        if (tid == 0) miss_out[b] = (float)s_miss;
    }
}

// ---------------- launch ----------------
extern "C" void kernel_launch(void* const* d_in, const int* in_sizes, int n_in,
                              void* d_out, int out_size) {
    const float* gt = (const float*)d_in[0];
    const int* gcls = (const int*)d_in[1];
    const float* pr = (const float*)d_in[2];
    float* out = (float*)d_out;

    float* miss_out = out + (size_t)B * R * 5 + (size_t)B * R * 2 + (size_t)B * R * 5;

    k_init<<<8, 256>>>();
    k_main<<<NB, 512>>>(gt, gcls, pr, out, miss_out);
}